// round 15
// baseline (speedup 1.0000x reference)
#include <cuda_runtime.h>
#include <cuda_fp16.h>
#include <cstdint>

#define EPS 1e-5f

__device__ __half g_Wh[384 * 256];
__device__ float g_bnsc[384];
__device__ float g_bnsh[384];
__device__ uint4 g_c16[(32u * 256u * 4096u) / 8u];   // 67 MB fp16 copy of c

// ---- branch C (mblk 1,2: c16-only): A resident 8x8KB, B16 ring 4x8KB ----
#define C_A   0u
#define C_B   65536u
// ---- branch M (mblk 0: q uses x, v uses c16): A 3x8, Bx16 2x8, Bc16 3x8, stgx 3x16 ----
#define M_A   0u
#define M_BX  24576u
#define M_BC  40960u
#define M_SX  65536u
#define SMEM_TOTAL 114688   // 112 KB -> 2 CTAs/SM

__device__ __forceinline__ uint32_t swzA32(uint32_t o) { return o ^ ((o >> 3) & 0x30); }
__device__ __forceinline__ uint32_t swzB(uint32_t o)   { return o ^ ((o >> 4) & 0x70); }

__device__ __forceinline__ uint32_t s2u(const void* p) {
    uint32_t a;
    asm("{ .reg .u64 t; cvta.to.shared.u64 t, %1; cvt.u32.u64 %0, t; }" : "=r"(a) : "l"(p));
    return a;
}
__device__ __forceinline__ void ldsm_x4(uint32_t* r, uint32_t a) {
    asm volatile("ldmatrix.sync.aligned.m8n8.x4.shared.b16 {%0,%1,%2,%3}, [%4];"
                 : "=r"(r[0]), "=r"(r[1]), "=r"(r[2]), "=r"(r[3]) : "r"(a));
}
__device__ __forceinline__ void ldsm_x4t(uint32_t* r, uint32_t a) {
    asm volatile("ldmatrix.sync.aligned.m8n8.x4.trans.shared.b16 {%0,%1,%2,%3}, [%4];"
                 : "=r"(r[0]), "=r"(r[1]), "=r"(r[2]), "=r"(r[3]) : "r"(a));
}
__device__ __forceinline__ void mma16816(float* d, const uint32_t* a, const uint32_t* b) {
    asm volatile("mma.sync.aligned.m16n8k16.row.col.f32.f16.f16.f32 "
                 "{%0,%1,%2,%3}, {%4,%5,%6,%7}, {%8,%9}, {%0,%1,%2,%3};"
                 : "+f"(d[0]), "+f"(d[1]), "+f"(d[2]), "+f"(d[3])
                 : "r"(a[0]), "r"(a[1]), "r"(a[2]), "r"(a[3]), "r"(b[0]), "r"(b[1]));
}
__device__ __forceinline__ void cpa16(uint32_t dst, const void* src) {
    asm volatile("cp.async.cg.shared.global [%0], [%1], 16;" :: "r"(dst), "l"(src));
}
__device__ __forceinline__ void cpa_commit() { asm volatile("cp.async.commit_group;"); }

// ---------------- prep: W fp32 -> fp16, fold BN ----------------
__global__ void prep_kernel(const float* __restrict__ Wq, const float* __restrict__ Wv,
                            const float* __restrict__ Wk,
                            const float* __restrict__ qg, const float* __restrict__ qb,
                            const float* __restrict__ qm, const float* __restrict__ qv,
                            const float* __restrict__ vg, const float* __restrict__ vb,
                            const float* __restrict__ vm, const float* __restrict__ vv)
{
    int idx = blockIdx.x * blockDim.x + threadIdx.x;
    int stride = gridDim.x * blockDim.x;
    for (int i = idx; i < 384 * 256; i += stride) {
        int r = i >> 8, k = i & 255;
        float w = (r < 64) ? Wq[(r << 8) | k]
                : (r < 320) ? Wv[((r - 64) << 8) | k]
                            : Wk[((r - 320) << 8) | k];
        g_Wh[i] = __float2half_rn(w);
    }
    if (idx < 384) {
        float sc = 1.f, sh = 0.f;
        if (idx < 320) {
            float g, b, m, v;
            if (idx < 64) { g = qg[idx]; b = qb[idx]; m = qm[idx]; v = qv[idx]; }
            else { g = vg[idx-64]; b = vb[idx-64]; m = vm[idx-64]; v = vv[idx-64]; }
            sc = g * rsqrtf(v + EPS);
            sh = b - m * sc;
        }
        g_bnsc[idx] = sc; g_bnsh[idx] = sh;
    }
}

// ---------------- pre-pass: c fp32 -> fp16 (streaming) ----------------
__global__ void conv_c_kernel(const float* __restrict__ c)
{
    const int n = (32 * 256 * 4096) / 8;              // 4,194,304 uint4 outputs
    int idx = blockIdx.x * blockDim.x + threadIdx.x;
    int stride = gridDim.x * blockDim.x;
    const float4* src = (const float4*)c;
    for (int i = idx; i < n; i += stride) {
        float4 v0 = src[2 * i], v1 = src[2 * i + 1];
        __half2 h0 = __floats2half2_rn(v0.x, v0.y);
        __half2 h1 = __floats2half2_rn(v0.z, v0.w);
        __half2 h2 = __floats2half2_rn(v1.x, v1.y);
        __half2 h3 = __floats2half2_rn(v1.z, v1.w);
        g_c16[i] = make_uint4(*(uint32_t*)&h0, *(uint32_t*)&h1,
                              *(uint32_t*)&h2, *(uint32_t*)&h3);
    }
}

// ---------------- shared epilogue ----------------
__device__ __forceinline__ void epilogue_store(
    float d[2][8][4], float* __restrict__ out,
    int b, int pxb, int ch0, int mw, int nw, int lane, bool isK)
{
    const int g = lane >> 2, cc = lane & 3;
    #pragma unroll
    for (int mt = 0; mt < 2; mt++) {
        const int chA = ch0 + (mw << 5) + (mt << 4) + g;
        float* oA = out + ((size_t)b * 384 + chA) * 4096 + pxb + (nw << 6);
        float* oB = oA + (size_t)8 * 4096;
        if (!isK) {
            float s0 = g_bnsc[chA],     h0 = g_bnsh[chA];
            float s1 = g_bnsc[chA + 8], h1 = g_bnsh[chA + 8];
            #pragma unroll
            for (int nt = 0; nt < 8; nt++) {
                int col = (nt << 3) + (cc << 1);
                *(float2*)(oA + col) = make_float2(fmaf(d[mt][nt][0], s0, h0),
                                                   fmaf(d[mt][nt][1], s0, h0));
                *(float2*)(oB + col) = make_float2(fmaf(d[mt][nt][2], s1, h1),
                                                   fmaf(d[mt][nt][3], s1, h1));
            }
        } else {
            float mx0 = -3.4e38f, mx1 = -3.4e38f;
            #pragma unroll
            for (int nt = 0; nt < 8; nt++) {
                mx0 = fmaxf(mx0, fmaxf(d[mt][nt][0], d[mt][nt][1]));
                mx1 = fmaxf(mx1, fmaxf(d[mt][nt][2], d[mt][nt][3]));
            }
            mx0 = fmaxf(mx0, __shfl_xor_sync(0xffffffffu, mx0, 1));
            mx0 = fmaxf(mx0, __shfl_xor_sync(0xffffffffu, mx0, 2));
            mx1 = fmaxf(mx1, __shfl_xor_sync(0xffffffffu, mx1, 1));
            mx1 = fmaxf(mx1, __shfl_xor_sync(0xffffffffu, mx1, 2));
            float s0 = 0.f, s1 = 0.f;
            #pragma unroll
            for (int nt = 0; nt < 8; nt++) {
                d[mt][nt][0] = __expf(d[mt][nt][0] - mx0); s0 += d[mt][nt][0];
                d[mt][nt][1] = __expf(d[mt][nt][1] - mx0); s0 += d[mt][nt][1];
                d[mt][nt][2] = __expf(d[mt][nt][2] - mx1); s1 += d[mt][nt][2];
                d[mt][nt][3] = __expf(d[mt][nt][3] - mx1); s1 += d[mt][nt][3];
            }
            s0 += __shfl_xor_sync(0xffffffffu, s0, 1);
            s0 += __shfl_xor_sync(0xffffffffu, s0, 2);
            s1 += __shfl_xor_sync(0xffffffffu, s1, 1);
            s1 += __shfl_xor_sync(0xffffffffu, s1, 2);
            float i0 = __frcp_rn(s0), i1 = __frcp_rn(s1);
            #pragma unroll
            for (int nt = 0; nt < 8; nt++) {
                int col = (nt << 3) + (cc << 1);
                *(float2*)(oA + col) = make_float2(d[mt][nt][0] * i0, d[mt][nt][1] * i0);
                *(float2*)(oB + col) = make_float2(d[mt][nt][2] * i1, d[mt][nt][3] * i1);
            }
        }
    }
}

// ---------------- main kernel ----------------
__global__ __launch_bounds__(256, 2)
void main_kernel(const float* __restrict__ x, float* __restrict__ out)
{
    extern __shared__ char smem[];
    const uint32_t sb = s2u(smem);
    const int tid = threadIdx.x, wid = tid >> 5, lane = tid & 31;
    const int mw = wid >> 1, nw = wid & 1;           // warp grid 4(M) x 2(N)
    const int bid = blockIdx.x;
    const int mblk = bid % 3;                        // ch blocks 0-127 / 128-255 / 256-383
    const int tile = bid / 3;
    const int b = tile >> 5, pxb = (tile & 31) << 7;
    const int ch0 = mblk << 7;
    const char* c16 = (const char*)g_c16;

    float d[2][8][4];
    #pragma unroll
    for (int mt = 0; mt < 2; mt++)
        #pragma unroll
        for (int nt = 0; nt < 8; nt++)
            d[mt][nt][0] = d[mt][nt][1] = d[mt][nt][2] = d[mt][nt][3] = 0.f;

    if (mblk != 0) {
        // ===== branch C: c16-only, A resident, 4-deep direct B ring, 1 barrier/chunk =====
        // resident A: all 8 K-chunks, one cp.async group
        #pragma unroll
        for (int i = 0; i < 16; i++) {
            int idx = tid + (i << 8);                // 4096 granules
            int ck = idx >> 9, j = idx & 511, r = j >> 2, u = j & 3;
            cpa16(sb + C_A + (uint32_t)(ck << 13) + swzA32((uint32_t)((r << 6) + (u << 4))),
                  g_Wh + ((ch0 + r) << 8) + (ck << 5) + (u << 3));
        }
        cpa_commit();

        auto issueB = [&](int ck) {                  // 512 granules of 16B, fp16 direct
            const uint32_t bsel = C_B + (uint32_t)((ck & 3) << 13);
            #pragma unroll
            for (int i = 0; i < 2; i++) {
                int idx = tid + (i << 8);
                int kk = idx >> 4, p = idx & 15;
                cpa16(sb + bsel + swzB((uint32_t)((kk << 8) + (p << 4))),
                      c16 + ((size_t)((b << 8) + (ck << 5) + kk) * 4096 + pxb + (p << 3)) * 2);
            }
            cpa_commit();
        };
        issueB(0); issueB(1); issueB(2);
        asm volatile("cp.async.wait_group 2;");      // A + B0 landed

        #pragma unroll
        for (int ck = 0; ck < 8; ck++) {
            __syncthreads();                         // publish A(+B[ck]) to all
            if (ck + 3 < 8) issueB(ck + 3);          // writes buf (ck-1)&3, free since last iter

            const uint32_t abuf = sb + C_A + (uint32_t)(ck << 13);
            const uint32_t bbuf = sb + C_B + (uint32_t)((ck & 3) << 13);
            #pragma unroll
            for (int ks = 0; ks < 2; ks++) {
                uint32_t a[2][4], bf[8][2];
                #pragma unroll
                for (int mt = 0; mt < 2; mt++) {
                    int row = (mw << 5) + (mt << 4) + (lane & 15);
                    int kb  = (ks << 5) + ((lane >> 4) << 4);
                    ldsm_x4(a[mt], abuf + swzA32((uint32_t)((row << 6) + kb)));
                }
                #pragma unroll
                for (int p = 0; p < 4; p++) {
                    int krow = (ks << 4) + (lane & 15);
                    int ncol = (nw << 6) + (p << 4) + ((lane >> 4) << 3);
                    uint32_t r[4];
                    ldsm_x4t(r, bbuf + swzB((uint32_t)((krow << 8) + (ncol << 1))));
                    bf[2*p][0] = r[0]; bf[2*p][1] = r[1];
                    bf[2*p+1][0] = r[2]; bf[2*p+1][1] = r[3];
                }
                #pragma unroll
                for (int mt = 0; mt < 2; mt++)
                    #pragma unroll
                    for (int nt = 0; nt < 8; nt++)
                        mma16816(d[mt][nt], a[mt], bf[nt]);
            }
            // late wait: ensure B[ck+1] landed (per-thread) before next sync publishes it
            if (ck + 3 < 8)      { asm volatile("cp.async.wait_group 2;"); }
            else if (ck + 2 < 8) { asm volatile("cp.async.wait_group 1;"); }
            else if (ck + 1 < 8) { asm volatile("cp.async.wait_group 0;"); }
        }
        epilogue_store(d, out, b, pxb, ch0, mw, nw, lane, (mblk == 2 && mw >= 2));
    } else {
        // ===== branch M: q(x via staging+convert) + v(c16 direct), 1 barrier/chunk =====
        auto issue = [&](int ck) {                   // one group: A + stgx + Bc16
            const int kc = ck << 5;
            const uint32_t asel = M_A + (uint32_t)(ck % 3) * 8192u;
            #pragma unroll
            for (int i = 0; i < 2; i++) {            // A: 512 granules
                int idx = tid + (i << 8);
                int r = idx >> 2, u = idx & 3;
                cpa16(sb + asel + swzA32((uint32_t)((r << 6) + (u << 4))),
                      g_Wh + (r << 8) + kc + (u << 3));
            }
            const uint32_t ssel = M_SX + (uint32_t)(ck % 3) * 16384u;
            #pragma unroll
            for (int i = 0; i < 4; i++) {            // stg x: 1024 granules
                int idx = tid + (i << 8);
                int kk = idx >> 5, p = idx & 31;
                cpa16(sb + ssel + (uint32_t)((kk << 9) + (p << 4)),
                      x + (size_t)((b << 8) + kc + kk) * 4096 + pxb + (p << 2));
            }
            const uint32_t bcs = M_BC + (uint32_t)(ck % 3) * 8192u;
            #pragma unroll
            for (int i = 0; i < 2; i++) {            // Bc16 direct: 512 granules
                int idx = tid + (i << 8);
                int kk = idx >> 4, p = idx & 15;
                cpa16(sb + bcs + swzB((uint32_t)((kk << 8) + (p << 4))),
                      c16 + ((size_t)((b << 8) + kc + kk) * 4096 + pxb + (p << 3)) * 2);
            }
            cpa_commit();
        };
        auto convertx = [&](int ck) {                // reads only self-written granules
            const uint32_t ssel = M_SX + (uint32_t)(ck % 3) * 16384u;
            const uint32_t bsel = M_BX + (uint32_t)(ck & 1) * 8192u;
            #pragma unroll
            for (int i = 0; i < 4; i++) {
                int idx = tid + (i << 8);
                int kk = idx >> 5, p = idx & 31;
                float4 v = *(const float4*)(smem + ssel + (kk << 9) + (p << 4));
                __half2 h0 = __floats2half2_rn(v.x, v.y);
                __half2 h1 = __floats2half2_rn(v.z, v.w);
                *(uint2*)(smem + bsel + swzB((uint32_t)((kk << 8) + (p << 3)))) =
                    make_uint2(*(uint32_t*)&h0, *(uint32_t*)&h1);
            }
        };

        issue(0); issue(1);
        asm volatile("cp.async.wait_group 1;");
        convertx(0);

        #pragma unroll
        for (int ck = 0; ck < 8; ck++) {
            __syncthreads();                         // publish A[ck], Bc16[ck], Bx16[ck]
            if (ck + 2 < 8) issue(ck + 2);
            if (ck + 1 < 8) {
                if (ck + 2 < 8) { asm volatile("cp.async.wait_group 1;"); }
                else            { asm volatile("cp.async.wait_group 0;"); }
                convertx(ck + 1);                    // overlaps compute(ck)
            }
            const uint32_t abuf = sb + M_A + (uint32_t)(ck % 3) * 8192u;
            const uint32_t bbuf = (mw < 2) ? sb + M_BX + (uint32_t)(ck & 1) * 8192u
                                           : sb + M_BC + (uint32_t)(ck % 3) * 8192u;
            #pragma unroll
            for (int ks = 0; ks < 2; ks++) {
                uint32_t a[2][4], bf[8][2];
                #pragma unroll
                for (int mt = 0; mt < 2; mt++) {
                    int row = (mw << 5) + (mt << 4) + (lane & 15);
                    int kb  = (ks << 5) + ((lane >> 4) << 4);
                    ldsm_x4(a[mt], abuf + swzA32((uint32_t)((row << 6) + kb)));
                }
                #pragma unroll
                for (int p = 0; p < 4; p++) {
                    int krow = (ks << 4) + (lane & 15);
                    int ncol = (nw << 6) + (p << 4) + ((lane >> 4) << 3);
                    uint32_t r[4];
                    ldsm_x4t(r, bbuf + swzB((uint32_t)((krow << 8) + (ncol << 1))));
                    bf[2*p][0] = r[0]; bf[2*p][1] = r[1];
                    bf[2*p+1][0] = r[2]; bf[2*p+1][1] = r[3];
                }
                #pragma unroll
                for (int mt = 0; mt < 2; mt++)
                    #pragma unroll
                    for (int nt = 0; nt < 8; nt++)
                        mma16816(d[mt][nt], a[mt], bf[nt]);
            }
        }
        epilogue_store(d, out, b, pxb, 0, mw, nw, lane, false);
    }
}

extern "C" void kernel_launch(void* const* d_in, const int* in_sizes, int n_in,
                              void* d_out, int out_size)
{
    const float* x = (const float*)d_in[0];
    const float* c = (const float*)d_in[1];
    prep_kernel<<<96, 256>>>((const float*)d_in[2], (const float*)d_in[3],
                             (const float*)d_in[4], (const float*)d_in[5],
                             (const float*)d_in[6], (const float*)d_in[7],
                             (const float*)d_in[8], (const float*)d_in[9],
                             (const float*)d_in[10], (const float*)d_in[11],
                             (const float*)d_in[12]);
    conv_c_kernel<<<2048, 256>>>(c);
    cudaFuncSetAttribute(main_kernel, cudaFuncAttributeMaxDynamicSharedMemorySize, SMEM_TOTAL);
    main_kernel<<<3072, 256, SMEM_TOTAL>>>(x, (float*)d_out);
}

// round 16
// speedup vs baseline: 1.1224x; 1.1224x over previous
#include <cuda_runtime.h>
#include <cuda_fp16.h>
#include <cstdint>

#define EPS 1e-5f

__device__ __half g_Wh[384 * 256];
__device__ float g_bnsc[384];
__device__ float g_bnsh[384];

// ---- branch C (mblk 1,2: c-only, K32, 4-stage, convert-ahead) ----
#define C_A   0u        // A fp16: 4 bufs x 128 rows x 64B (swzA32) = 32 KB
#define C_B   32768u    // B fp16 c: 2 bufs x 32 rows x 256B (swzB) = 16 KB
#define C_S   49152u    // staging fp32 c: 4 bufs x 16 KB           = 64 KB
// ---- branch M (mblk 0: x+c, K32, 2-stage == R13) ----
#define M_A   0u        // 2 x 8 KB
#define M_BX  16384u    // 2 x 8 KB
#define M_BC  32768u    // 2 x 8 KB
#define M_SX  49152u    // 2 x 16 KB
#define M_SC  81920u    // 2 x 16 KB
#define SMEM_TOTAL 114688   // 112 KB -> 2 CTAs/SM

__device__ __forceinline__ uint32_t swzA32(uint32_t o) { return o ^ ((o >> 3) & 0x30); }
__device__ __forceinline__ uint32_t swzB(uint32_t o)   { return o ^ ((o >> 4) & 0x70); }

__device__ __forceinline__ uint32_t s2u(const void* p) {
    uint32_t a;
    asm("{ .reg .u64 t; cvta.to.shared.u64 t, %1; cvt.u32.u64 %0, t; }" : "=r"(a) : "l"(p));
    return a;
}
__device__ __forceinline__ void ldsm_x4(uint32_t* r, uint32_t a) {
    asm volatile("ldmatrix.sync.aligned.m8n8.x4.shared.b16 {%0,%1,%2,%3}, [%4];"
                 : "=r"(r[0]), "=r"(r[1]), "=r"(r[2]), "=r"(r[3]) : "r"(a));
}
__device__ __forceinline__ void ldsm_x4t(uint32_t* r, uint32_t a) {
    asm volatile("ldmatrix.sync.aligned.m8n8.x4.trans.shared.b16 {%0,%1,%2,%3}, [%4];"
                 : "=r"(r[0]), "=r"(r[1]), "=r"(r[2]), "=r"(r[3]) : "r"(a));
}
__device__ __forceinline__ void mma16816(float* d, const uint32_t* a, const uint32_t* b) {
    asm volatile("mma.sync.aligned.m16n8k16.row.col.f32.f16.f16.f32 "
                 "{%0,%1,%2,%3}, {%4,%5,%6,%7}, {%8,%9}, {%0,%1,%2,%3};"
                 : "+f"(d[0]), "+f"(d[1]), "+f"(d[2]), "+f"(d[3])
                 : "r"(a[0]), "r"(a[1]), "r"(a[2]), "r"(a[3]), "r"(b[0]), "r"(b[1]));
}
__device__ __forceinline__ void cpa16(uint32_t dst, const void* src) {
    asm volatile("cp.async.cg.shared.global [%0], [%1], 16;" :: "r"(dst), "l"(src));
}
__device__ __forceinline__ void cpa_commit() { asm volatile("cp.async.commit_group;"); }

// ---------------- prep: W fp32 -> fp16, fold BN ----------------
__global__ void prep_kernel(const float* __restrict__ Wq, const float* __restrict__ Wv,
                            const float* __restrict__ Wk,
                            const float* __restrict__ qg, const float* __restrict__ qb,
                            const float* __restrict__ qm, const float* __restrict__ qv,
                            const float* __restrict__ vg, const float* __restrict__ vb,
                            const float* __restrict__ vm, const float* __restrict__ vv)
{
    int idx = blockIdx.x * blockDim.x + threadIdx.x;
    int stride = gridDim.x * blockDim.x;
    for (int i = idx; i < 384 * 256; i += stride) {
        int r = i >> 8, k = i & 255;
        float w = (r < 64) ? Wq[(r << 8) | k]
                : (r < 320) ? Wv[((r - 64) << 8) | k]
                            : Wk[((r - 320) << 8) | k];
        g_Wh[i] = __float2half_rn(w);
    }
    if (idx < 384) {
        float sc = 1.f, sh = 0.f;
        if (idx < 320) {
            float g, b, m, v;
            if (idx < 64) { g = qg[idx]; b = qb[idx]; m = qm[idx]; v = qv[idx]; }
            else { g = vg[idx-64]; b = vb[idx-64]; m = vm[idx-64]; v = vv[idx-64]; }
            sc = g * rsqrtf(v + EPS);
            sh = b - m * sc;
        }
        g_bnsc[idx] = sc; g_bnsh[idx] = sh;
    }
}

// ---------------- shared epilogue ----------------
__device__ __forceinline__ void epilogue_store(
    float d[2][8][4], float* __restrict__ out,
    int b, int pxb, int ch0, int mw, int nw, int lane, bool isK)
{
    const int g = lane >> 2, cc = lane & 3;
    #pragma unroll
    for (int mt = 0; mt < 2; mt++) {
        const int chA = ch0 + (mw << 5) + (mt << 4) + g;
        float* oA = out + ((size_t)b * 384 + chA) * 4096 + pxb + (nw << 6);
        float* oB = oA + (size_t)8 * 4096;
        if (!isK) {
            float s0 = g_bnsc[chA],     h0 = g_bnsh[chA];
            float s1 = g_bnsc[chA + 8], h1 = g_bnsh[chA + 8];
            #pragma unroll
            for (int nt = 0; nt < 8; nt++) {
                int col = (nt << 3) + (cc << 1);
                *(float2*)(oA + col) = make_float2(fmaf(d[mt][nt][0], s0, h0),
                                                   fmaf(d[mt][nt][1], s0, h0));
                *(float2*)(oB + col) = make_float2(fmaf(d[mt][nt][2], s1, h1),
                                                   fmaf(d[mt][nt][3], s1, h1));
            }
        } else {
            float mx0 = -3.4e38f, mx1 = -3.4e38f;
            #pragma unroll
            for (int nt = 0; nt < 8; nt++) {
                mx0 = fmaxf(mx0, fmaxf(d[mt][nt][0], d[mt][nt][1]));
                mx1 = fmaxf(mx1, fmaxf(d[mt][nt][2], d[mt][nt][3]));
            }
            mx0 = fmaxf(mx0, __shfl_xor_sync(0xffffffffu, mx0, 1));
            mx0 = fmaxf(mx0, __shfl_xor_sync(0xffffffffu, mx0, 2));
            mx1 = fmaxf(mx1, __shfl_xor_sync(0xffffffffu, mx1, 1));
            mx1 = fmaxf(mx1, __shfl_xor_sync(0xffffffffu, mx1, 2));
            float s0 = 0.f, s1 = 0.f;
            #pragma unroll
            for (int nt = 0; nt < 8; nt++) {
                d[mt][nt][0] = __expf(d[mt][nt][0] - mx0); s0 += d[mt][nt][0];
                d[mt][nt][1] = __expf(d[mt][nt][1] - mx0); s0 += d[mt][nt][1];
                d[mt][nt][2] = __expf(d[mt][nt][2] - mx1); s1 += d[mt][nt][2];
                d[mt][nt][3] = __expf(d[mt][nt][3] - mx1); s1 += d[mt][nt][3];
            }
            s0 += __shfl_xor_sync(0xffffffffu, s0, 1);
            s0 += __shfl_xor_sync(0xffffffffu, s0, 2);
            s1 += __shfl_xor_sync(0xffffffffu, s1, 1);
            s1 += __shfl_xor_sync(0xffffffffu, s1, 2);
            float i0 = __frcp_rn(s0), i1 = __frcp_rn(s1);
            #pragma unroll
            for (int nt = 0; nt < 8; nt++) {
                int col = (nt << 3) + (cc << 1);
                *(float2*)(oA + col) = make_float2(d[mt][nt][0] * i0, d[mt][nt][1] * i0);
                *(float2*)(oB + col) = make_float2(d[mt][nt][2] * i1, d[mt][nt][3] * i1);
            }
        }
    }
}

// ---------------- main kernel ----------------
__global__ __launch_bounds__(256, 2)
void main_kernel(const float* __restrict__ x, const float* __restrict__ c,
                 float* __restrict__ out)
{
    extern __shared__ char smem[];
    const uint32_t sb = s2u(smem);
    const int tid = threadIdx.x, wid = tid >> 5, lane = tid & 31;
    const int mw = wid >> 1, nw = wid & 1;           // warp grid 4(M) x 2(N)
    const int bid = blockIdx.x;
    const int mblk = bid % 3;
    const int tile = bid / 3;
    const int b = tile >> 5, pxb = (tile & 31) << 7;
    const int ch0 = mblk << 7;

    float d[2][8][4];
    #pragma unroll
    for (int mt = 0; mt < 2; mt++)
        #pragma unroll
        for (int nt = 0; nt < 8; nt++)
            d[mt][nt][0] = d[mt][nt][1] = d[mt][nt][2] = d[mt][nt][3] = 0.f;

    if (mblk != 0) {
        // ===== branch C: c-only, K32, 4-stage ring, convert-ahead, 1 barrier/chunk =====
        auto issue = [&](int ck) {                    // 1 group: A(ck) + stg(ck), ring %4
            const int kc = ck << 5;
            const uint32_t asel = C_A + (uint32_t)((ck & 3) << 13);
            #pragma unroll
            for (int i = 0; i < 2; i++) {             // A: 512 granules
                int idx = tid + (i << 8);
                int r = idx >> 2, u = idx & 3;
                cpa16(sb + asel + swzA32((uint32_t)((r << 6) + (u << 4))),
                      g_Wh + ((ch0 + r) << 8) + kc + (u << 3));
            }
            const uint32_t ssel = C_S + (uint32_t)((ck & 3) << 14);
            #pragma unroll
            for (int i = 0; i < 4; i++) {             // stg c: 1024 granules
                int idx = tid + (i << 8);
                int kk = idx >> 5, p = idx & 31;
                cpa16(sb + ssel + (uint32_t)((kk << 9) + (p << 4)),
                      c + (size_t)((b << 8) + kc + kk) * 4096 + pxb + (p << 2));
            }
            cpa_commit();
        };
        auto convert = [&](int ck) {                  // reads only self-written granules
            const uint32_t ssel = C_S + (uint32_t)((ck & 3) << 14);
            const uint32_t bsel = C_B + (uint32_t)((ck & 1) << 13);
            #pragma unroll
            for (int i = 0; i < 4; i++) {
                int idx = tid + (i << 8);
                int kk = idx >> 5, p = idx & 31;
                float4 v = *(const float4*)(smem + ssel + (kk << 9) + (p << 4));
                __half2 h0 = __floats2half2_rn(v.x, v.y);
                __half2 h1 = __floats2half2_rn(v.z, v.w);
                *(uint2*)(smem + bsel + swzB((uint32_t)((kk << 8) + (p << 3)))) =
                    make_uint2(*(uint32_t*)&h0, *(uint32_t*)&h1);
            }
        };

        issue(0); issue(1); issue(2);
        asm volatile("cp.async.wait_group 2;");       // chunk 0 landed; 1,2 in flight
        convert(0);

        #pragma unroll
        for (int ck = 0; ck < 8; ck++) {
            __syncthreads();                          // publish A[ck], B16[ck]
            if (ck + 3 < 8) issue(ck + 3);            // ring slot (ck+3)&3 == (ck-1)&3, free
            if (ck + 1 < 8) {
                // confirm chunk ck+1; leave {ck+2, ck+3} (when present) in flight
                if (ck <= 4)      { asm volatile("cp.async.wait_group 2;"); }
                else if (ck == 5) { asm volatile("cp.async.wait_group 1;"); }
                else              { asm volatile("cp.async.wait_group 0;"); }
                convert(ck + 1);                      // overlaps compute(ck) below
            }
            const uint32_t abuf = sb + C_A + (uint32_t)((ck & 3) << 13);
            const uint32_t bbuf = sb + C_B + (uint32_t)((ck & 1) << 13);
            #pragma unroll
            for (int ks = 0; ks < 2; ks++) {
                uint32_t a[2][4], bf[8][2];
                #pragma unroll
                for (int mt = 0; mt < 2; mt++) {
                    int row = (mw << 5) + (mt << 4) + (lane & 15);
                    int kb  = (ks << 5) + ((lane >> 4) << 4);
                    ldsm_x4(a[mt], abuf + swzA32((uint32_t)((row << 6) + kb)));
                }
                #pragma unroll
                for (int p = 0; p < 4; p++) {
                    int krow = (ks << 4) + (lane & 15);
                    int ncol = (nw << 6) + (p << 4) + ((lane >> 4) << 3);
                    uint32_t r[4];
                    ldsm_x4t(r, bbuf + swzB((uint32_t)((krow << 8) + (ncol << 1))));
                    bf[2*p][0] = r[0]; bf[2*p][1] = r[1];
                    bf[2*p+1][0] = r[2]; bf[2*p+1][1] = r[3];
                }
                #pragma unroll
                for (int mt = 0; mt < 2; mt++)
                    #pragma unroll
                    for (int nt = 0; nt < 8; nt++)
                        mma16816(d[mt][nt], a[mt], bf[nt]);
            }
        }
        epilogue_store(d, out, b, pxb, ch0, mw, nw, lane, (mblk == 2 && mw >= 2));
    } else {
        // ===== branch M: x+c, K32, 2-stage (R13 verbatim) =====
        const uint32_t offB = (mw < 2) ? M_BX : M_BC; // q uses x; v uses c
        auto issue = [&](int ck) {
            const int kc = ck << 5;
            const uint32_t sel13 = (uint32_t)((ck & 1) << 13);
            const uint32_t sel14 = (uint32_t)((ck & 1) << 14);
            #pragma unroll
            for (int i = 0; i < 2; i++) {
                int idx = tid + (i << 8);
                int r = idx >> 2, u = idx & 3;
                cpa16(sb + M_A + sel13 + swzA32((uint32_t)((r << 6) + (u << 4))),
                      g_Wh + (r << 8) + kc + (u << 3));
            }
            #pragma unroll
            for (int i = 0; i < 4; i++) {
                int idx = tid + (i << 8);
                int kk = idx >> 5, p = idx & 31;
                size_t go = (size_t)((b << 8) + kc + kk) * 4096 + pxb + (p << 2);
                uint32_t so = (uint32_t)((kk << 9) + (p << 4));
                cpa16(sb + M_SC + sel14 + so, c + go);
                cpa16(sb + M_SX + sel14 + so, x + go);
            }
            cpa_commit();
        };
        auto convert_one = [&](uint32_t stg, uint32_t dst16) {
            #pragma unroll
            for (int i = 0; i < 4; i++) {
                int idx = tid + (i << 8);
                int kk = idx >> 5, p = idx & 31;
                float4 v = *(const float4*)(smem + stg + (kk << 9) + (p << 4));
                __half2 h0 = __floats2half2_rn(v.x, v.y);
                __half2 h1 = __floats2half2_rn(v.z, v.w);
                *(uint2*)(smem + dst16 + swzB((uint32_t)((kk << 8) + (p << 3)))) =
                    make_uint2(*(uint32_t*)&h0, *(uint32_t*)&h1);
            }
        };

        issue(0);
        #pragma unroll
        for (int ck = 0; ck < 8; ck++) {
            asm volatile("cp.async.wait_group 0;");
            __syncthreads();
            if (ck < 7) issue(ck + 1);
            const uint32_t sel13 = (uint32_t)((ck & 1) << 13);
            const uint32_t sel14 = (uint32_t)((ck & 1) << 14);
            convert_one(M_SC + sel14, M_BC + sel13);
            convert_one(M_SX + sel14, M_BX + sel13);
            __syncthreads();

            const uint32_t abuf = sb + M_A + sel13;
            const uint32_t bbuf = sb + offB + sel13;
            #pragma unroll
            for (int ks = 0; ks < 2; ks++) {
                uint32_t a[2][4], bf[8][2];
                #pragma unroll
                for (int mt = 0; mt < 2; mt++) {
                    int row = (mw << 5) + (mt << 4) + (lane & 15);
                    int kb  = (ks << 5) + ((lane >> 4) << 4);
                    ldsm_x4(a[mt], abuf + swzA32((uint32_t)((row << 6) + kb)));
                }
                #pragma unroll
                for (int p = 0; p < 4; p++) {
                    int krow = (ks << 4) + (lane & 15);
                    int ncol = (nw << 6) + (p << 4) + ((lane >> 4) << 3);
                    uint32_t r[4];
                    ldsm_x4t(r, bbuf + swzB((uint32_t)((krow << 8) + (ncol << 1))));
                    bf[2*p][0] = r[0]; bf[2*p][1] = r[1];
                    bf[2*p+1][0] = r[2]; bf[2*p+1][1] = r[3];
                }
                #pragma unroll
                for (int mt = 0; mt < 2; mt++)
                    #pragma unroll
                    for (int nt = 0; nt < 8; nt++)
                        mma16816(d[mt][nt], a[mt], bf[nt]);
            }
        }
        epilogue_store(d, out, b, pxb, 0, mw, nw, lane, false);
    }
}

extern "C" void kernel_launch(void* const* d_in, const int* in_sizes, int n_in,
                              void* d_out, int out_size)
{
    const float* x = (const float*)d_in[0];
    const float* c = (const float*)d_in[1];
    prep_kernel<<<96, 256>>>((const float*)d_in[2], (const float*)d_in[3],
                             (const float*)d_in[4], (const float*)d_in[5],
                             (const float*)d_in[6], (const float*)d_in[7],
                             (const float*)d_in[8], (const float*)d_in[9],
                             (const float*)d_in[10], (const float*)d_in[11],
                             (const float*)d_in[12]);
    cudaFuncSetAttribute(main_kernel, cudaFuncAttributeMaxDynamicSharedMemorySize, SMEM_TOTAL);
    main_kernel<<<3072, 256, SMEM_TOTAL>>>(x, c, (float*)d_out);
}